// round 14
// baseline (speedup 1.0000x reference)
#include <cuda_runtime.h>
#include <cstdint>

#define VOCAB 50000
#define EDIM  256
#define HDIM  256
#define BATCH 64
#define TLEN  2048

#define CANARY 0x7FC00BADu

typedef unsigned long long u64;

// proj_table[v][h] = sum_e emb[v][e] * W_ih[h][e]   (51.2 MB device scratch)
__device__ float g_proj[VOCAB * HDIM];

// ---------------------------------------------------------------------------
// Kernel A: proj = emb @ W_ih^T   (NT SGEMM, C[50000,256])  -- unchanged
// ---------------------------------------------------------------------------
__global__ __launch_bounds__(256) void proj_kernel(const float* __restrict__ emb,
                                                   const float* __restrict__ Wih) {
    __shared__ float As[32][128];
    __shared__ float Bs[32][128];

    const int n0 = blockIdx.x * 128;
    const int m0 = blockIdx.y * 128;
    const int tid = threadIdx.x;
    const int tx = tid & 15;
    const int ty = tid >> 4;

    float acc[8][8];
#pragma unroll
    for (int a = 0; a < 8; a++)
#pragma unroll
        for (int bb = 0; bb < 8; bb++) acc[a][bb] = 0.0f;

    for (int kc = 0; kc < EDIM; kc += 32) {
#pragma unroll
        for (int q = 0; q < 4; q++) {
            int fid = tid + 256 * q;
            int row = fid >> 3;
            int col = fid & 7;
            float4 av = make_float4(0.f, 0.f, 0.f, 0.f);
            int m = m0 + row;
            if (m < VOCAB)
                av = __ldg((const float4*)(emb + (size_t)m * EDIM + kc + col * 4));
            As[col * 4 + 0][row] = av.x;
            As[col * 4 + 1][row] = av.y;
            As[col * 4 + 2][row] = av.z;
            As[col * 4 + 3][row] = av.w;
            float4 bv = __ldg((const float4*)(Wih + (size_t)(n0 + row) * EDIM + kc + col * 4));
            Bs[col * 4 + 0][row] = bv.x;
            Bs[col * 4 + 1][row] = bv.y;
            Bs[col * 4 + 2][row] = bv.z;
            Bs[col * 4 + 3][row] = bv.w;
        }
        __syncthreads();

#pragma unroll
        for (int k = 0; k < 32; k++) {
            float a[8], b[8];
            *(float4*)&a[0] = *(const float4*)&As[k][ty * 8];
            *(float4*)&a[4] = *(const float4*)&As[k][ty * 8 + 4];
            *(float4*)&b[0] = *(const float4*)&Bs[k][tx * 8];
            *(float4*)&b[4] = *(const float4*)&Bs[k][tx * 8 + 4];
#pragma unroll
            for (int ii = 0; ii < 8; ii++)
#pragma unroll
                for (int jj = 0; jj < 8; jj++) acc[ii][jj] += a[ii] * b[jj];
        }
        __syncthreads();
    }

#pragma unroll
    for (int ii = 0; ii < 8; ii++) {
        int m = m0 + ty * 8 + ii;
        if (m < VOCAB) {
            float4 v0 = make_float4(acc[ii][0], acc[ii][1], acc[ii][2], acc[ii][3]);
            float4 v1 = make_float4(acc[ii][4], acc[ii][5], acc[ii][6], acc[ii][7]);
            *(float4*)(g_proj + (size_t)m * HDIM + n0 + tx * 8)     = v0;
            *(float4*)(g_proj + (size_t)m * HDIM + n0 + tx * 8 + 4) = v1;
        }
    }
}

// ---------------------------------------------------------------------------
// Kernel B: RNN scan. 64 clusters x 2 CTAs x 1024 threads.
// R12 structure with the bar3 epoch hazard fixed: bar3 is a FULL sync for
// both the tail and the peer-half warps (640 threads), so peer-half can
// never arrive for epoch t+1 before the tail syncs epoch t.
//   warps 0-3   tail: own slice 0 + reduce + tanh + stores + poison
//   warps 4-15  own-half producers: slices 1-3 -> ps, bar2.arrive
//   warps 16-31 peer-half: lane-partitioned canary poll -> FMA -> ps ->
//               bar3.SYNC (epoch-aligned with tail)
// bar4(512): step open for warps 0-15. No in-loop __syncthreads.
// ps parity-buffered; poison by the tail after bar3 (ordered before its
// remote send; peer's next overwrite is >=2 DSMEM flights + a step later).
// ---------------------------------------------------------------------------
__device__ __forceinline__ void fma2(u64& acc, u64 a, u64 b) {
    asm("fma.rn.f32x2 %0, %1, %2, %0;" : "+l"(acc) : "l"(a), "l"(b));
}
__device__ __forceinline__ uint32_t s2u(const void* p) {
    return (uint32_t)__cvta_generic_to_shared(p);
}
__device__ __forceinline__ uint32_t mapa_u32(uint32_t a, uint32_t r) {
    uint32_t ret;
    asm("mapa.shared::cluster.u32 %0, %1, %2;" : "=r"(ret) : "r"(a), "r"(r));
    return ret;
}
__device__ __forceinline__ void st_remote_f32(uint32_t ra, float v) {
    asm volatile("st.shared::cluster.f32 [%0], %1;" :: "r"(ra), "f"(v) : "memory");
}
__device__ __forceinline__ uint4 ldsv4_vol(uint32_t a) {
    uint4 r;
    asm volatile("ld.volatile.shared.v4.u32 {%0, %1, %2, %3}, [%4];"
                 : "=r"(r.x), "=r"(r.y), "=r"(r.z), "=r"(r.w) : "r"(a) : "memory");
    return r;
}
__device__ __forceinline__ void bar_sync_named(int bid, int cnt) {
    asm volatile("bar.sync %0, %1;" :: "r"(bid), "r"(cnt) : "memory");
}
__device__ __forceinline__ void bar_arrive_named(int bid, int cnt) {
    asm volatile("bar.arrive %0, %1;" :: "r"(bid), "r"(cnt) : "memory");
}
__device__ __forceinline__ void cl_arrive() {
    asm volatile("barrier.cluster.arrive.aligned;" ::: "memory");
}
__device__ __forceinline__ void cl_wait() {
    asm volatile("barrier.cluster.wait.aligned;" ::: "memory");
}
// exact-enough tanh (validated rel_err ~2.8e-7 end-to-end, R5-R11)
__device__ __forceinline__ float fast_tanh(float x) {
    float xc = fminf(fmaxf(x, -15.0f), 15.0f);
    float e  = __expf(2.0f * xc);
    return __fdividef(e - 1.0f, e + 1.0f);
}

__global__ void __cluster_dims__(2, 1, 1) __launch_bounds__(1024, 1)
scan_kernel(const int* __restrict__ reviews, const int* __restrict__ lengths,
            const float* __restrict__ Whh, const float* __restrict__ Wcls,
            const float* __restrict__ bcls, float* __restrict__ out) {
    __shared__ __align__(16) float hbuf[2][HDIM];   // full h, double-buffered
    __shared__ float ps[2][8][128];                 // parity-buffered partials
    __shared__ int toks[TLEN];

    const int tid  = threadIdx.x;
    const int warp = tid >> 5;
    const int lane = tid & 31;
    const int i    = tid & 127;             // output index within the half
    const int b    = blockIdx.x >> 1;
    const int rank = blockIdx.x & 1;
    const int peer = rank ^ 1;
    const int len  = lengths[b];
    const int ownK  = rank * 128;           // h range produced locally
    const int peerK = 128 - ownK;

    // slice assignment: warps 0-15 own half (slice 0..3), 16-31 peer half
    const bool isPeerGrp = (warp >= 16);
    const int  sl    = isPeerGrp ? ((warp - 16) >> 2) : (warp >> 2);
    const int  kbase = (isPeerGrp ? peerK : ownK) + sl * 32;

    for (int idx = tid; idx < TLEN; idx += 1024)
        toks[idx] = reviews[b * TLEN + idx];
    if (tid < HDIM) hbuf[0][tid] = 0.0f;                        // t=0 state
    if (tid < 128)  hbuf[1][peerK + tid] = __uint_as_float(CANARY);  // armed

    // W_hh[ownK + i][kbase .. kbase+31] as 16 packed f32x2
    u64 w[16];
    {
        const u64* wp = (const u64*)(Whh + (size_t)(ownK + i) * HDIM + kbase);
#pragma unroll
        for (int q = 0; q < 16; q++) w[q] = wp[q];
    }
    __syncthreads();
    cl_arrive(); cl_wait();                 // peer's canary init visible

    // remote h slots for the tail threads (both phases)
    uint32_t rH0 = 0, rH1 = 0;
    if (tid < 128) {
        rH0 = mapa_u32(s2u(&hbuf[0][ownK + tid]), peer);
        rH1 = mapa_u32(s2u(&hbuf[1][ownK + tid]), peer);
    }
    // poll addresses: lane l watches hbuf[x][peerK + 4l .. +3] (covers all 128)
    const uint32_t pa0 = s2u(&hbuf[0][peerK + 4 * lane]);
    const uint32_t pa1 = s2u(&hbuf[1][peerK + 4 * lane]);

    float xp_cur = 0.0f;
    if (tid < 128) xp_cur = __ldg(g_proj + (size_t)toks[0] * HDIM + ownK + tid);

    for (int t = 0; t < len; ++t) {
        const int p = t & 1, pn = p ^ 1;

        if (!isPeerGrp) {
            bar_sync_named(4, 512);         // local h(t) ready (warps 0-15)

            if (warp < 4) {
                // ------------- tail: slice 0 + serial tail ------------------
                int tn = (t + 1 < len) ? (t + 1) : t;
                float xp_next =
                    __ldg(g_proj + (size_t)toks[tn] * HDIM + ownK + tid);

                u64 a0 = 0ull, a1 = 0ull;
                const ulonglong2* hp = (const ulonglong2*)&hbuf[p][kbase];
#pragma unroll
                for (int q = 0; q < 8; q++) {
                    ulonglong2 hh = hp[q];
                    fma2(a0, w[2 * q],     hh.x);
                    fma2(a1, w[2 * q + 1], hh.y);
                }
                float2 f0 = *(float2*)&a0, f1 = *(float2*)&a1;
                float own0 = (f0.x + f0.y) + (f1.x + f1.y);

                bar_sync_named(2, 512);     // own-half ps ready
                float sum = xp_cur + own0 +
                            ps[p][1][i] + ps[p][2][i] + ps[p][3][i];
                bar_sync_named(3, 640);     // peer-half ps ready (epoch-aligned)
                // poison buf[p] peer half; precedes our send in program order
                hbuf[p][peerK + tid] = __uint_as_float(CANARY);
                sum += ps[p][4][i] + ps[p][5][i] + ps[p][6][i] + ps[p][7][i];
                float v = fast_tanh(sum);
                st_remote_f32(pn ? rH1 : rH0, v);   // long-latency first
                hbuf[pn][ownK + tid] = v;           // local copy
                xp_cur = xp_next;
            } else {
                // ------------- own-half producers ---------------------------
                u64 a0 = 0ull, a1 = 0ull;
                const ulonglong2* hp = (const ulonglong2*)&hbuf[p][kbase];
#pragma unroll
                for (int q = 0; q < 8; q++) {
                    ulonglong2 hh = hp[q];
                    fma2(a0, w[2 * q],     hh.x);
                    fma2(a1, w[2 * q + 1], hh.y);
                }
                float2 f0 = *(float2*)&a0, f1 = *(float2*)&a1;
                ps[p][sl][i] = (f0.x + f0.y) + (f1.x + f1.y);
                bar_arrive_named(2, 512);
            }
        } else {
            // ------------- peer-half warps: data-paced, epoch-bounded -------
            const uint32_t pa = p ? pa1 : pa0;
            for (;;) {                      // direct poll: covers all 128 floats
                uint4 c = ldsv4_vol(pa);
                bool ok = (c.x != CANARY) & (c.y != CANARY) &
                          (c.z != CANARY) & (c.w != CANARY);
                if (__all_sync(0xffffffffu, ok)) break;
            }
            u64 a0 = 0ull, a1 = 0ull;
            const ulonglong2* hp = (const ulonglong2*)&hbuf[p][kbase];
#pragma unroll
            for (int q = 0; q < 8; q++) {
                ulonglong2 hh = hp[q];
                fma2(a0, w[2 * q],     hh.x);
                fma2(a1, w[2 * q + 1], hh.y);
            }
            float2 f0 = *(float2*)&a0, f1 = *(float2*)&a1;
            ps[p][4 + sl][i] = (f0.x + f0.y) + (f1.x + f1.y);
            bar_sync_named(3, 640);         // FULL sync: epoch-aligns with tail
        }
    }
    __syncthreads();                        // final local h visible CTA-wide

    // classifier: rank 0 assembles full final h (poll peer half of final buf)
    if (rank == 0 && tid < 64) {
        const float* hf = hbuf[len & 1];
        int c = tid >> 5, ln = tid & 31;
        uint32_t a4 = s2u(&hf[ln + 128]);
        uint32_t a5 = s2u(&hf[ln + 160]);
        uint32_t a6 = s2u(&hf[ln + 192]);
        uint32_t a7 = s2u(&hf[ln + 224]);
        uint32_t u4, u5, u6, u7;
        for (;;) {
            asm volatile("ld.volatile.shared.u32 %0, [%1];" : "=r"(u4) : "r"(a4));
            asm volatile("ld.volatile.shared.u32 %0, [%1];" : "=r"(u5) : "r"(a5));
            asm volatile("ld.volatile.shared.u32 %0, [%1];" : "=r"(u6) : "r"(a6));
            asm volatile("ld.volatile.shared.u32 %0, [%1];" : "=r"(u7) : "r"(a7));
            if ((u4 != CANARY) & (u5 != CANARY) & (u6 != CANARY) & (u7 != CANARY))
                break;
        }
        float sum = 0.0f;
#pragma unroll
        for (int m = 0; m < 4; m++)
            sum += Wcls[c * HDIM + ln + 32 * m] * hf[ln + 32 * m];
        sum += Wcls[c * HDIM + ln + 128] * __uint_as_float(u4);
        sum += Wcls[c * HDIM + ln + 160] * __uint_as_float(u5);
        sum += Wcls[c * HDIM + ln + 192] * __uint_as_float(u6);
        sum += Wcls[c * HDIM + ln + 224] * __uint_as_float(u7);
#pragma unroll
        for (int o = 16; o > 0; o >>= 1) sum += __shfl_down_sync(0xffffffffu, sum, o);
        if (ln == 0) out[b * 2 + c] = sum + bcls[c];
    }

    // keep both CTAs alive until all cross-CTA traffic has landed
    cl_arrive(); cl_wait();
}

// ---------------------------------------------------------------------------
extern "C" void kernel_launch(void* const* d_in, const int* in_sizes, int n_in,
                              void* d_out, int out_size) {
    const int*   reviews = (const int*)d_in[0];
    const int*   lengths = (const int*)d_in[1];
    const float* emb     = (const float*)d_in[2];
    const float* Wih     = (const float*)d_in[3];
    const float* Whh     = (const float*)d_in[4];
    const float* Wcls    = (const float*)d_in[5];
    const float* bcls    = (const float*)d_in[6];
    float*       out     = (float*)d_out;

    dim3 gA(2, (VOCAB + 127) / 128);
    proj_kernel<<<gA, 256>>>(emb, Wih);

    scan_kernel<<<BATCH * 2, 1024>>>(reviews, lengths, Whh, Wcls, bcls, out);
}

// round 15
// speedup vs baseline: 1.0679x; 1.0679x over previous
#include <cuda_runtime.h>
#include <cstdint>

#define VOCAB 50000
#define EDIM  256
#define HDIM  256
#define BATCH 64
#define TLEN  2048

#define CANARY 0x7FC00BADu

typedef unsigned long long u64;

// proj_table[v][h] = sum_e emb[v][e] * W_ih[h][e]   (51.2 MB device scratch)
__device__ float g_proj[VOCAB * HDIM];

// ---------------------------------------------------------------------------
// Kernel A: proj = emb @ W_ih^T   (NT SGEMM, C[50000,256])  -- unchanged
// ---------------------------------------------------------------------------
__global__ __launch_bounds__(256) void proj_kernel(const float* __restrict__ emb,
                                                   const float* __restrict__ Wih) {
    __shared__ float As[32][128];
    __shared__ float Bs[32][128];

    const int n0 = blockIdx.x * 128;
    const int m0 = blockIdx.y * 128;
    const int tid = threadIdx.x;
    const int tx = tid & 15;
    const int ty = tid >> 4;

    float acc[8][8];
#pragma unroll
    for (int a = 0; a < 8; a++)
#pragma unroll
        for (int bb = 0; bb < 8; bb++) acc[a][bb] = 0.0f;

    for (int kc = 0; kc < EDIM; kc += 32) {
#pragma unroll
        for (int q = 0; q < 4; q++) {
            int fid = tid + 256 * q;
            int row = fid >> 3;
            int col = fid & 7;
            float4 av = make_float4(0.f, 0.f, 0.f, 0.f);
            int m = m0 + row;
            if (m < VOCAB)
                av = __ldg((const float4*)(emb + (size_t)m * EDIM + kc + col * 4));
            As[col * 4 + 0][row] = av.x;
            As[col * 4 + 1][row] = av.y;
            As[col * 4 + 2][row] = av.z;
            As[col * 4 + 3][row] = av.w;
            float4 bv = __ldg((const float4*)(Wih + (size_t)(n0 + row) * EDIM + kc + col * 4));
            Bs[col * 4 + 0][row] = bv.x;
            Bs[col * 4 + 1][row] = bv.y;
            Bs[col * 4 + 2][row] = bv.z;
            Bs[col * 4 + 3][row] = bv.w;
        }
        __syncthreads();

#pragma unroll
        for (int k = 0; k < 32; k++) {
            float a[8], b[8];
            *(float4*)&a[0] = *(const float4*)&As[k][ty * 8];
            *(float4*)&a[4] = *(const float4*)&As[k][ty * 8 + 4];
            *(float4*)&b[0] = *(const float4*)&Bs[k][tx * 8];
            *(float4*)&b[4] = *(const float4*)&Bs[k][tx * 8 + 4];
#pragma unroll
            for (int ii = 0; ii < 8; ii++)
#pragma unroll
                for (int jj = 0; jj < 8; jj++) acc[ii][jj] += a[ii] * b[jj];
        }
        __syncthreads();
    }

#pragma unroll
    for (int ii = 0; ii < 8; ii++) {
        int m = m0 + ty * 8 + ii;
        if (m < VOCAB) {
            float4 v0 = make_float4(acc[ii][0], acc[ii][1], acc[ii][2], acc[ii][3]);
            float4 v1 = make_float4(acc[ii][4], acc[ii][5], acc[ii][6], acc[ii][7]);
            *(float4*)(g_proj + (size_t)m * HDIM + n0 + tx * 8)     = v0;
            *(float4*)(g_proj + (size_t)m * HDIM + n0 + tx * 8 + 4) = v1;
        }
    }
}

// ---------------------------------------------------------------------------
// Kernel B: RNN scan. 64 clusters x 2 CTAs x 1024 threads.
// Decoupled warp groups (R12/R13) + R11's single-poll-warp (R13's regression
// was 16 polling warps). No in-loop __syncthreads, no bar5.
//   warps 0-3   tail: own slice 0 + reduce + tanh + stores + poison
//   warps 4-15  own-half producers: ps -> bar2.arrive
//   warps 16-31 peer-half: warp16 polls + bar1.arrive, 17-31 bar1.sync;
//               FMA -> ps -> bar3.SYNC(640) (epoch-aligned with tail)
//   bar4(512):  step open for warps 0-15 (tail's prior stores visible)
// ps parity-buffered. Poison by tail after bar3, before its remote send.
// ---------------------------------------------------------------------------
__device__ __forceinline__ void fma2(u64& acc, u64 a, u64 b) {
    asm("fma.rn.f32x2 %0, %1, %2, %0;" : "+l"(acc) : "l"(a), "l"(b));
}
__device__ __forceinline__ uint32_t s2u(const void* p) {
    return (uint32_t)__cvta_generic_to_shared(p);
}
__device__ __forceinline__ uint32_t mapa_u32(uint32_t a, uint32_t r) {
    uint32_t ret;
    asm("mapa.shared::cluster.u32 %0, %1, %2;" : "=r"(ret) : "r"(a), "r"(r));
    return ret;
}
__device__ __forceinline__ void st_remote_f32(uint32_t ra, float v) {
    asm volatile("st.shared::cluster.f32 [%0], %1;" :: "r"(ra), "f"(v) : "memory");
}
__device__ __forceinline__ uint4 ldsv4_vol(uint32_t a) {
    uint4 r;
    asm volatile("ld.volatile.shared.v4.u32 {%0, %1, %2, %3}, [%4];"
                 : "=r"(r.x), "=r"(r.y), "=r"(r.z), "=r"(r.w) : "r"(a) : "memory");
    return r;
}
__device__ __forceinline__ void bar_sync_named(int bid, int cnt) {
    asm volatile("bar.sync %0, %1;" :: "r"(bid), "r"(cnt) : "memory");
}
__device__ __forceinline__ void bar_arrive_named(int bid, int cnt) {
    asm volatile("bar.arrive %0, %1;" :: "r"(bid), "r"(cnt) : "memory");
}
__device__ __forceinline__ void cl_arrive() {
    asm volatile("barrier.cluster.arrive.aligned;" ::: "memory");
}
__device__ __forceinline__ void cl_wait() {
    asm volatile("barrier.cluster.wait.aligned;" ::: "memory");
}
// exact-enough tanh (validated rel_err ~2.8e-7 end-to-end, R5-R13)
__device__ __forceinline__ float fast_tanh(float x) {
    float xc = fminf(fmaxf(x, -15.0f), 15.0f);
    float e  = __expf(2.0f * xc);
    return __fdividef(e - 1.0f, e + 1.0f);
}

__global__ void __cluster_dims__(2, 1, 1) __launch_bounds__(1024, 1)
scan_kernel(const int* __restrict__ reviews, const int* __restrict__ lengths,
            const float* __restrict__ Whh, const float* __restrict__ Wcls,
            const float* __restrict__ bcls, float* __restrict__ out) {
    __shared__ __align__(16) float hbuf[2][HDIM];   // full h, double-buffered
    __shared__ float ps[2][8][128];                 // parity-buffered partials
    __shared__ int toks[TLEN];

    const int tid  = threadIdx.x;
    const int warp = tid >> 5;
    const int lane = tid & 31;
    const int i    = tid & 127;             // output index within the half
    const int b    = blockIdx.x >> 1;
    const int rank = blockIdx.x & 1;
    const int peer = rank ^ 1;
    const int len  = lengths[b];
    const int ownK  = rank * 128;           // h range produced locally
    const int peerK = 128 - ownK;

    // slice assignment: warps 0-15 own half (slice 0..3), 16-31 peer half
    const bool isPeerGrp = (warp >= 16);
    const int  sl    = isPeerGrp ? ((warp - 16) >> 2) : (warp >> 2);
    const int  kbase = (isPeerGrp ? peerK : ownK) + sl * 32;

    for (int idx = tid; idx < TLEN; idx += 1024)
        toks[idx] = reviews[b * TLEN + idx];
    if (tid < HDIM) hbuf[0][tid] = 0.0f;                        // t=0 state
    if (tid < 128)  hbuf[1][peerK + tid] = __uint_as_float(CANARY);  // armed

    // W_hh[ownK + i][kbase .. kbase+31] as 16 packed f32x2
    u64 w[16];
    {
        const u64* wp = (const u64*)(Whh + (size_t)(ownK + i) * HDIM + kbase);
#pragma unroll
        for (int q = 0; q < 16; q++) w[q] = wp[q];
    }
    __syncthreads();
    cl_arrive(); cl_wait();                 // peer's canary init visible

    // remote h slots for the tail threads (both phases)
    uint32_t rH0 = 0, rH1 = 0;
    if (tid < 128) {
        rH0 = mapa_u32(s2u(&hbuf[0][ownK + tid]), peer);
        rH1 = mapa_u32(s2u(&hbuf[1][ownK + tid]), peer);
    }
    // poll addresses (warp 16): lane l watches hbuf[x][peerK + 4l .. +3]
    const uint32_t pa0 = s2u(&hbuf[0][peerK + 4 * lane]);
    const uint32_t pa1 = s2u(&hbuf[1][peerK + 4 * lane]);

    float xp_cur = 0.0f;
    if (tid < 128) xp_cur = __ldg(g_proj + (size_t)toks[0] * HDIM + ownK + tid);

    for (int t = 0; t < len; ++t) {
        const int p = t & 1, pn = p ^ 1;

        if (!isPeerGrp) {
            bar_sync_named(4, 512);         // local h(t) ready (warps 0-15)

            if (warp < 4) {
                // ------------- tail: slice 0 + serial tail ------------------
                int tn = (t + 1 < len) ? (t + 1) : t;
                float xp_next =
                    __ldg(g_proj + (size_t)toks[tn] * HDIM + ownK + tid);

                u64 a0 = 0ull, a1 = 0ull;
                const ulonglong2* hp = (const ulonglong2*)&hbuf[p][kbase];
#pragma unroll
                for (int q = 0; q < 8; q++) {
                    ulonglong2 hh = hp[q];
                    fma2(a0, w[2 * q],     hh.x);
                    fma2(a1, w[2 * q + 1], hh.y);
                }
                float2 f0 = *(float2*)&a0, f1 = *(float2*)&a1;
                float own0 = (f0.x + f0.y) + (f1.x + f1.y);

                bar_sync_named(2, 512);     // own-half ps ready
                float sum = xp_cur + own0 +
                            ps[p][1][i] + ps[p][2][i] + ps[p][3][i];
                bar_sync_named(3, 640);     // peer-half ps ready (epoch-aligned)
                // poison buf[p] peer half; precedes our send in program order
                hbuf[p][peerK + tid] = __uint_as_float(CANARY);
                sum += ps[p][4][i] + ps[p][5][i] + ps[p][6][i] + ps[p][7][i];
                float v = fast_tanh(sum);
                st_remote_f32(pn ? rH1 : rH0, v);   // long-latency first
                hbuf[pn][ownK + tid] = v;           // local copy
                xp_cur = xp_next;
            } else {
                // ------------- own-half producers ---------------------------
                u64 a0 = 0ull, a1 = 0ull;
                const ulonglong2* hp = (const ulonglong2*)&hbuf[p][kbase];
#pragma unroll
                for (int q = 0; q < 8; q++) {
                    ulonglong2 hh = hp[q];
                    fma2(a0, w[2 * q],     hh.x);
                    fma2(a1, w[2 * q + 1], hh.y);
                }
                float2 f0 = *(float2*)&a0, f1 = *(float2*)&a1;
                ps[p][sl][i] = (f0.x + f0.y) + (f1.x + f1.y);
                bar_arrive_named(2, 512);
            }
        } else {
            // ------------- peer-half warps: single poll warp + release ------
            if (warp == 16) {
                const uint32_t pa = p ? pa1 : pa0;
                for (;;) {                  // covers all 128 floats (4/lane)
                    uint4 c = ldsv4_vol(pa);
                    bool ok = (c.x != CANARY) & (c.y != CANARY) &
                              (c.z != CANARY) & (c.w != CANARY);
                    if (__all_sync(0xffffffffu, ok)) break;
                }
                bar_arrive_named(1, 512);   // last contributor: release, no wait
            } else {
                bar_sync_named(1, 512);     // wait for poll warp
            }
            u64 a0 = 0ull, a1 = 0ull;
            const ulonglong2* hp = (const ulonglong2*)&hbuf[p][kbase];
#pragma unroll
            for (int q = 0; q < 8; q++) {
                ulonglong2 hh = hp[q];
                fma2(a0, w[2 * q],     hh.x);
                fma2(a1, w[2 * q + 1], hh.y);
            }
            float2 f0 = *(float2*)&a0, f1 = *(float2*)&a1;
            ps[p][4 + sl][i] = (f0.x + f0.y) + (f1.x + f1.y);
            bar_sync_named(3, 640);         // FULL sync: epoch-aligns with tail
        }
    }
    __syncthreads();                        // final local h visible CTA-wide

    // classifier: rank 0 assembles full final h (poll peer half of final buf)
    if (rank == 0 && tid < 64) {
        const float* hf = hbuf[len & 1];
        int c = tid >> 5, ln = tid & 31;
        uint32_t a4 = s2u(&hf[ln + 128]);
        uint32_t a5 = s2u(&hf[ln + 160]);
        uint32_t a6 = s2u(&hf[ln + 192]);
        uint32_t a7 = s2u(&hf[ln + 224]);
        uint32_t u4, u5, u6, u7;
        for (;;) {
            asm volatile("ld.volatile.shared.u32 %0, [%1];" : "=r"(u4) : "r"(a4));
            asm volatile("ld.volatile.shared.u32 %0, [%1];" : "=r"(u5) : "r"(a5));
            asm volatile("ld.volatile.shared.u32 %0, [%1];" : "=r"(u6) : "r"(a6));
            asm volatile("ld.volatile.shared.u32 %0, [%1];" : "=r"(u7) : "r"(a7));
            if ((u4 != CANARY) & (u5 != CANARY) & (u6 != CANARY) & (u7 != CANARY))
                break;
        }
        float sum = 0.0f;
#pragma unroll
        for (int m = 0; m < 4; m++)
            sum += Wcls[c * HDIM + ln + 32 * m] * hf[ln + 32 * m];
        sum += Wcls[c * HDIM + ln + 128] * __uint_as_float(u4);
        sum += Wcls[c * HDIM + ln + 160] * __uint_as_float(u5);
        sum += Wcls[c * HDIM + ln + 192] * __uint_as_float(u6);
        sum += Wcls[c * HDIM + ln + 224] * __uint_as_float(u7);
#pragma unroll
        for (int o = 16; o > 0; o >>= 1) sum += __shfl_down_sync(0xffffffffu, sum, o);
        if (ln == 0) out[b * 2 + c] = sum + bcls[c];
    }

    // keep both CTAs alive until all cross-CTA traffic has landed
    cl_arrive(); cl_wait();
}

// ---------------------------------------------------------------------------
extern "C" void kernel_launch(void* const* d_in, const int* in_sizes, int n_in,
                              void* d_out, int out_size) {
    const int*   reviews = (const int*)d_in[0];
    const int*   lengths = (const int*)d_in[1];
    const float* emb     = (const float*)d_in[2];
    const float* Wih     = (const float*)d_in[3];
    const float* Whh     = (const float*)d_in[4];
    const float* Wcls    = (const float*)d_in[5];
    const float* bcls    = (const float*)d_in[6];
    float*       out     = (float*)d_out;

    dim3 gA(2, (VOCAB + 127) / 128);
    proj_kernel<<<gA, 256>>>(emb, Wih);

    scan_kernel<<<BATCH * 2, 1024>>>(reviews, lengths, Whh, Wcls, bcls, out);
}